// round 16
// baseline (speedup 1.0000x reference)
#include <cuda_runtime.h>
#include <cuda_fp16.h>
#include <cstdint>

#define ROWS_TOTAL 16384
#define DMODEL 256
#define MAT_ELEMS (ROWS_TOTAL * DMODEL)
#define QPB 8                      // queries per attention block

// ---------------------------------------------------------------------------
// Scratch (static device arrays — no allocation in kernel_launch).
// ---------------------------------------------------------------------------
__device__ __align__(16) __half g_Proj[3 * MAT_ELEMS];      // 0=Kh, 1=Vh, 2=Qh (fp16)
__device__ __align__(16) __half g_Ihh[2 * MAT_ELEMS];       // fp16 inputs: 0=K, 1=Q
__device__ __align__(16) __half g_AVhh[MAT_ELEMS];          // attention output (fp16)
__device__ __align__(16) __half g_Wt[4 * 65536];            // fp16 weights^T: [Wk,Wv,Wq,Wo][n][k]

// ---------------------------------------------------------------------------
// PTX primitives (base-target: ldmatrix sm_75+, fp16 mma sm_80+, cp.async sm_80+)
// ---------------------------------------------------------------------------
__device__ __forceinline__ uint32_t smem_to_u32(const void* smem_ptr) {
    uint32_t addr;
    asm("{ .reg .u64 tmp; cvta.to.shared.u64 tmp, %1; cvt.u32.u64 %0, tmp; }"
        : "=r"(addr) : "l"(smem_ptr));
    return addr;
}

#define LDMATRIX_X4(r0, r1, r2, r3, addr) \
    asm volatile("ldmatrix.sync.aligned.m8n8.x4.shared.b16 {%0,%1,%2,%3}, [%4];" \
                 : "=r"(r0), "=r"(r1), "=r"(r2), "=r"(r3) : "r"(addr))

#define MMA_F16(d, a, b) \
    asm volatile("mma.sync.aligned.m16n8k16.row.col.f32.f16.f16.f32 " \
                 "{%0,%1,%2,%3}, {%4,%5,%6,%7}, {%8,%9}, {%0,%1,%2,%3};" \
                 : "+f"((d)[0]), "+f"((d)[1]), "+f"((d)[2]), "+f"((d)[3]) \
                 : "r"((a)[0]), "r"((a)[1]), "r"((a)[2]), "r"((a)[3]), \
                   "r"((b)[0]), "r"((b)[1]))

#define CP_ASYNC16(dst_u32, src_ptr) \
    asm volatile("cp.async.ca.shared.global [%0], [%1], 16;" \
                 :: "r"(dst_u32), "l"(src_ptr) : "memory")
#define CP_COMMIT() asm volatile("cp.async.commit_group;" ::: "memory")
#define CP_WAIT(n)  asm volatile("cp.async.wait_group %0;" :: "n"(n) : "memory")

// ---------------------------------------------------------------------------
// Fused prep: grid (4096, 3).
//   y=0: K -> fp16 (g_Ihh slot 0)      y=1: Q -> fp16 (g_Ihh slot 1)
//   y=2, x<1024: weight transpose Wt[mat][n][k] = fp16(W[k][n])
// ---------------------------------------------------------------------------
__global__ void __launch_bounds__(256) prep_kernel(
    const float* __restrict__ K, const float* __restrict__ Q,
    const float* __restrict__ Wk, const float* __restrict__ Wv,
    const float* __restrict__ Wq, const float* __restrict__ Wo)
{
    if (blockIdx.y < 2) {
        const float* src = blockIdx.y ? Q : K;
        __half* dst = g_Ihh + (size_t)blockIdx.y * MAT_ELEMS;
        const size_t i = ((size_t)blockIdx.x * 256 + threadIdx.x) * 4;
        float4 f = *(const float4*)&src[i];
        __half2 h0 = __floats2half2_rn(f.x, f.y);
        __half2 h1 = __floats2half2_rn(f.z, f.w);
        uint2 u;
        u.x = *reinterpret_cast<uint32_t*>(&h0);
        u.y = *reinterpret_cast<uint32_t*>(&h1);
        *(uint2*)&dst[i] = u;
    } else if (blockIdx.x < 1024) {
        const int mat = blockIdx.x >> 8;
        const float* W = (mat == 0) ? Wk : (mat == 1) ? Wv : (mat == 2) ? Wq : Wo;
        const int n = blockIdx.x & 255;
        const int k = threadIdx.x;
        g_Wt[mat * 65536 + n * 256 + k] = __float2half(W[k * 256 + n]);
    }
}

// ---------------------------------------------------------------------------
// fp16 HMMA GEMM body (cp.async double-buffered), shared by both kernels.
// BM=128, BN=128, BK=64, 256 threads (8 warps: 4m x 2n; warp tile 32x64).
// ALL A fragments preloaded per chunk; B via X4 covering nt-pairs, batched.
// Smem rows: 64 halves (128B) + 16B pad = 144B -> ldmatrix conflict-free.
// ---------------------------------------------------------------------------
#define A_OFF  0
#define W_OFF  18432              // 128 rows * 144B
#define BUF_SZ 36864
#define GSMEM  (2 * BUF_SZ)       // 73728

__device__ __forceinline__ void store_pair(float* C, size_t idx, float x, float y) {
    float2 o; o.x = x; o.y = y;
    *(float2*)&C[idx] = o;
}
__device__ __forceinline__ void store_pair(__half* C, size_t idx, float x, float y) {
    *(__half2*)&C[idx] = __floats2half2_rn(x, y);
}

template <typename OutT>
__device__ __forceinline__ void gemm_body(
    char* smem,
    const __half* __restrict__ A,
    const __half* __restrict__ Wt,
    const float* __restrict__ bias,
    OutT* __restrict__ C,
    int m0, int n0)
{
    const uint32_t sb = smem_to_u32(smem);
    const int tid    = threadIdx.x;
    const int lane   = tid & 31;
    const int wid    = tid >> 5;
    const int warp_m = wid & 3;
    const int warp_n = wid >> 2;

    float acc[2][8][4];
    #pragma unroll
    for (int mt = 0; mt < 2; mt++)
        #pragma unroll
        for (int nt = 0; nt < 8; nt++)
            #pragma unroll
            for (int i = 0; i < 4; i++) acc[mt][nt][i] = 0.f;

    const int st_r = tid >> 1;
    const int st_h = (tid & 1) * 32;
    const __half* a_base = &A[(size_t)(m0 + st_r) * DMODEL + st_h];
    const __half* w_base = &Wt[(size_t)(n0 + st_r) * DMODEL + st_h];
    const uint32_t st_off = (uint32_t)(st_r * 144 + st_h * 2);

    auto stage = [&](int c, uint32_t buf) {
        const int k0 = c * 64;
        #pragma unroll
        for (int i = 0; i < 4; i++) {
            CP_ASYNC16(buf + A_OFF + st_off + i * 16, a_base + k0 + i * 8);
            CP_ASYNC16(buf + W_OFF + st_off + i * 16, w_base + k0 + i * 8);
        }
    };

    const int aidx = lane >> 3;
    const int a_m  = (aidx & 1) * 8 + (lane & 7);
    const int a_k  = (aidx >> 1) * 8;
    const int b_r    = lane & 7;
    const int b_half = (lane >> 3) & 1;
    const int b_g    = lane >> 4;

    stage(0, sb);
    CP_COMMIT();

    for (int c = 0; c < 4; c++) {
        if (c < 3) {
            stage(c + 1, sb + (uint32_t)(((c + 1) & 1) * BUF_SZ));
            CP_COMMIT();
            CP_WAIT(1);
        } else {
            CP_WAIT(0);
        }
        __syncthreads();

        const uint32_t bb = sb + (uint32_t)((c & 1) * BUF_SZ);

        uint32_t af[2][4][4];
        #pragma unroll
        for (int mt = 0; mt < 2; mt++) {
            const uint32_t row = (uint32_t)(warp_m * 32 + mt * 16 + a_m);
            #pragma unroll
            for (int ks = 0; ks < 4; ks++) {
                const uint32_t col = (uint32_t)(ks * 16 + a_k) * 2u;
                LDMATRIX_X4(af[mt][ks][0], af[mt][ks][1], af[mt][ks][2], af[mt][ks][3],
                            bb + A_OFF + row * 144u + col);
            }
        }

        #pragma unroll
        for (int ks = 0; ks < 4; ks++) {
            uint32_t bf[4][4];
            #pragma unroll
            for (int nt2 = 0; nt2 < 4; nt2++) {
                const uint32_t row = (uint32_t)(warp_n * 64 + nt2 * 16 + b_g * 8 + b_r);
                const uint32_t col = (uint32_t)(ks * 16 + b_half * 8) * 2u;
                LDMATRIX_X4(bf[nt2][0], bf[nt2][1], bf[nt2][2], bf[nt2][3],
                            bb + W_OFF + row * 144u + col);
            }
            #pragma unroll
            for (int nt2 = 0; nt2 < 4; nt2++) {
                #pragma unroll
                for (int mt = 0; mt < 2; mt++) {
                    MMA_F16(acc[mt][2 * nt2 + 0], af[mt][ks], &bf[nt2][0]);
                    MMA_F16(acc[mt][2 * nt2 + 1], af[mt][ks], &bf[nt2][2]);
                }
            }
        }
        __syncthreads();
    }

    const int gr = lane >> 2;
    const int gc = (lane & 3) * 2;
    #pragma unroll
    for (int mt = 0; mt < 2; mt++) {
        const int mrow = m0 + warp_m * 32 + mt * 16 + gr;
        #pragma unroll
        for (int nt = 0; nt < 8; nt++) {
            const int ncol = n0 + warp_n * 64 + nt * 8 + gc;
            const float2 bv = *(const float2*)&bias[ncol];
            store_pair(C, (size_t)mrow * DMODEL + ncol,
                       acc[mt][nt][0] + bv.x, acc[mt][nt][1] + bv.y);
            store_pair(C, (size_t)(mrow + 8) * DMODEL + ncol,
                       acc[mt][nt][2] + bv.x, acc[mt][nt][3] + bv.y);
        }
    }
}

// Batched QKV projection: grid (2, 128, 3); z: 0=K-proj, 1=V-proj, 2=Q-proj.
__global__ void __launch_bounds__(256, 2) gemm_qkv_kernel(
    const float* __restrict__ bk, const float* __restrict__ bv,
    const float* __restrict__ bq)
{
    extern __shared__ __align__(16) char smem[];
    const int z = blockIdx.z;
    const __half* A = g_Ihh + (z == 2 ? (size_t)MAT_ELEMS : 0);
    const __half* W = g_Wt + (size_t)z * 65536;
    const float* bias = (z == 0) ? bk : (z == 1) ? bv : bq;
    __half* C = g_Proj + (size_t)z * MAT_ELEMS;
    gemm_body<__half>(smem, A, W, bias, C, blockIdx.y * 128, blockIdx.x * 128);
}

// Output projection: fp32 out.
__global__ void __launch_bounds__(256, 2) gemm_o_kernel(
    const float* __restrict__ bo, float* __restrict__ out)
{
    extern __shared__ __align__(16) char smem[];
    gemm_body<float>(smem, g_AVhh, g_Wt + 3 * 65536, bo, out,
                     blockIdx.y * 128, blockIdx.x * 128);
}

// ---------------------------------------------------------------------------
// kNN attention: QPB=8 queries per block (grid 2048), 8 warps.
// Init: neighbour offsets + Q rows for all 8 queries staged to smem once.
// Phase 1: per query, warp w -> neighbours 4w..4w+3, HFMA2 dot, quad-reduce.
// Phase 2: warp h: softmax for head h of all 8 queries (no max-sub: |e|<~4,
//          exp(e)/sum identical math, no overflow possible in fp32).
// Phase 3: warp (hp,grp): weights preloaded via LDS.64; fp16 chains of 4,
//          fp32 flush; cross-group combine via smem.
// ---------------------------------------------------------------------------
__global__ void __launch_bounds__(256) knn_attn_kernel(const int* __restrict__ nb)
{
    __shared__ float   Es[QPB][32][9];
    __shared__ __half2 As2[QPB][8][34];  // stride 34 -> 8B-aligned uint2 reads
    __shared__ float   Vred[QPB][4][64];
    __shared__ int     s_off[QPB][32];
    __shared__ __half2 Qs[QPB][128];     // 8 queries x 256 halves

    const int tid  = threadIdx.x;
    const int q0   = blockIdx.x * QPB;
    const int b    = q0 >> 13;           // 8192 % QPB == 0 -> whole block same batch
    const int w    = tid >> 5;
    const int lane = tid & 31;

    const __half* Khh = g_Proj;
    const __half* Vhh = g_Proj + MAT_ELEMS;
    const __half* Qhh = g_Proj + 2 * MAT_ELEMS;

    {
        const int qi = tid >> 5;
        const int j  = tid & 31;
        s_off[qi][j] = (((b << 13) + nb[(size_t)(q0 + qi) * 32 + j]) << 8);
        // stage 8 Q rows: 256 threads x 16B = 4096B, coalesced
        ((uint4*)Qs)[tid] = ((const uint4*)&Qhh[(size_t)q0 * DMODEL])[tid];
    }
    __syncthreads();

    // ---- Phase 1: scores ----
    #pragma unroll
    for (int qi = 0; qi < QPB; qi++) {
        uint4 qv = ((const uint4*)&Qs[qi][0])[lane];
        __half2 qh0 = *reinterpret_cast<__half2*>(&qv.x);
        __half2 qh1 = *reinterpret_cast<__half2*>(&qv.y);
        __half2 qh2 = *reinterpret_cast<__half2*>(&qv.z);
        __half2 qh3 = *reinterpret_cast<__half2*>(&qv.w);

        #pragma unroll
        for (int i = 0; i < 4; i++) {
            const int j = w * 4 + i;
            uint4 kv = *(const uint4*)&Khh[s_off[qi][j] + lane * 8];
            __half2 p2 = __hmul2(qh0, *reinterpret_cast<__half2*>(&kv.x));
            p2 = __hfma2(qh1, *reinterpret_cast<__half2*>(&kv.y), p2);
            p2 = __hfma2(qh2, *reinterpret_cast<__half2*>(&kv.z), p2);
            p2 = __hfma2(qh3, *reinterpret_cast<__half2*>(&kv.w), p2);
            float2 pf = __half22float2(p2);
            float p = pf.x + pf.y;
            p += __shfl_xor_sync(0xffffffffu, p, 1);
            p += __shfl_xor_sync(0xffffffffu, p, 2);
            if ((lane & 3) == 0) Es[qi][j][lane >> 2] = p * 0.0625f;  // 1/sqrt(256)
        }
    }
    __syncthreads();

    // ---- Phase 2: softmax (warp h, all queries; no max-sub needed) ----
    {
        const int h = w;
        #pragma unroll
        for (int qi = 0; qi < QPB; qi++) {
            float p = __expf(Es[qi][lane][h]);
            float s = p;
            #pragma unroll
            for (int o = 16; o > 0; o >>= 1)
                s += __shfl_xor_sync(0xffffffffu, s, o);
            As2[qi][h][lane] = __float2half2_rn(p / s);
        }
    }
    __syncthreads();

    // ---- Phase 3: AV (weights preloaded as LDS.64; fp16 chains of 4) ----
    {
        const int hp  = w & 3;         // head pair: heads 2hp, 2hp+1
        const int grp = w >> 2;        // neighbour group
        const int hl  = hp * 2 + (lane >> 4);
        const int col = hp * 64 + lane * 2;
        const __half* vcol = Vhh + col;

        float axs[QPB], ays[QPB];
        #pragma unroll
        for (int qi = 0; qi < QPB; qi++) {
            // preload 16 softmax weights (8 x LDS.64, broadcast within half-warp)
            uint2 wreg[8];
            const uint2* wrow = (const uint2*)&As2[qi][hl][grp * 16];
            #pragma unroll
            for (int i = 0; i < 8; i++) wreg[i] = wrow[i];
            const __half2* wh = (const __half2*)wreg;

            float ax = 0.f, ay = 0.f;
            #pragma unroll
            for (int blk = 0; blk < 4; blk++) {
                __half2 acc2 = __float2half2_rn(0.f);
                #pragma unroll
                for (int t = 0; t < 4; t++) {
                    const int j = grp * 16 + blk * 4 + t;
                    __half2 v2 = *(const __half2*)&vcol[s_off[qi][j]];
                    acc2 = __hfma2(wh[blk * 4 + t], v2, acc2);
                }
                float2 f = __half22float2(acc2);
                ax += f.x;
                ay += f.y;
            }
            axs[qi] = ax;
            ays[qi] = ay;
            if (grp == 1) {
                Vred[qi][hp][lane * 2 + 0] = ax;
                Vred[qi][hp][lane * 2 + 1] = ay;
            }
        }
        __syncthreads();
        if (grp == 0) {
            #pragma unroll
            for (int qi = 0; qi < QPB; qi++) {
                float ax = axs[qi] + Vred[qi][hp][lane * 2 + 0];
                float ay = ays[qi] + Vred[qi][hp][lane * 2 + 1];
                *(__half2*)&g_AVhh[(size_t)(q0 + qi) * DMODEL + col] =
                    __floats2half2_rn(ax, ay);
            }
        }
    }
}

// ---------------------------------------------------------------------------
extern "C" void kernel_launch(void* const* d_in, const int* in_sizes, int n_in,
                              void* d_out, int out_size)
{
    const float* Q  = (const float*)d_in[0];
    const float* K  = (const float*)d_in[1];
    const int*   nb = (const int*)d_in[2];
    const float* Wq = (const float*)d_in[3];
    const float* bq = (const float*)d_in[4];
    const float* Wk = (const float*)d_in[5];
    const float* bk = (const float*)d_in[6];
    const float* Wv = (const float*)d_in[7];
    const float* bv = (const float*)d_in[8];
    const float* Wo = (const float*)d_in[9];
    const float* bo = (const float*)d_in[10];
    float* out = (float*)d_out;

    cudaFuncSetAttribute(gemm_qkv_kernel,
                         cudaFuncAttributeMaxDynamicSharedMemorySize, GSMEM);
    cudaFuncSetAttribute(gemm_o_kernel,
                         cudaFuncAttributeMaxDynamicSharedMemorySize, GSMEM);

    // fused prep: fp16 convert (K,Q) + weight transpose (slot order Wk,Wv,Wq,Wo)
    dim3 pgrid(MAT_ELEMS / 1024, 3);
    prep_kernel<<<pgrid, 256>>>(K, Q, Wk, Wv, Wq, Wo);

    dim3 qkvgrid(2, 128, 3);
    gemm_qkv_kernel<<<qkvgrid, 256, GSMEM>>>(bk, bv, bq);

    knn_attn_kernel<<<16384 / QPB, 256>>>(nb);

    dim3 ogrid(2, 128);
    gemm_o_kernel<<<ogrid, 256, GSMEM>>>(bo, out);
}